// round 2
// baseline (speedup 1.0000x reference)
#include <cuda_runtime.h>
#include <cstdint>
#include <cstddef>

// RWW whole-brain sim, 8-CTA cluster, Con_Mtx register-resident.
// R2: cluster-mbarrier sync (2 alternating barriers, count=512),
//     packed fma.rn.f32x2 matvec, fast-math epilogue on all 4 lanes,
//     each lane broadcasts S_E to 2 CTAs (stores+arrives spread 4-wide).

#define NREG    512
#define NSTEPS  20000
#define NCTAS   8
#define ROWSPC  64
#define NTHR    256

// x-vector smem layout (floats): quarter stride QF floats (2576 B == 16 mod 128
// -> the 4 column-quarter lanes of a warp hit distinct 16B bank groups, 8-way bcast)
#define QF 644
#define PF 2576
#define XBYTES   (2 * PF * 4)          // 20608 B (two parity buffers)
#define MBAR_OFF XBYTES                // two mbarriers at 20608 / 20616
#define SMEM_BYTES (XBYTES + 16)

__device__ __forceinline__ unsigned long long ffma2(
    unsigned long long a, unsigned long long b, unsigned long long c) {
    unsigned long long d;
    asm("fma.rn.f32x2 %0, %1, %2, %3;" : "=l"(d) : "l"(a), "l"(b), "l"(c));
    return d;
}

__device__ __forceinline__ float fsum2(unsigned long long a) {
    float2 f = *reinterpret_cast<float2*>(&a);
    return f.x + f.y;
}

__device__ __forceinline__ float Hfun(float I, float a, float b, float d, float bigc) {
    float x     = fmaf(a, I, -b);
    float numer = fabsf(x) + 1e-9f;
    float neg   = -d * x;
    float e     = __expf(fminf(neg, 51.0f));
    float den_s = fabsf(1.0f - e) + 1e-9f * d;
    float den_b = fabsf(1.0f - bigc * neg) + 1e-9f * d;
    float denom = (neg > 50.0f) ? den_b : den_s;
    return __fdividef(numer, denom);
}

extern __shared__ float smx[];

__global__ void __launch_bounds__(NTHR, 1) __cluster_dims__(NCTAS, 1, 1)
rww_kernel(const float* __restrict__ init_state,   // (512, 2)
           const float* __restrict__ Con,          // (512, 512) row-major
           const float* __restrict__ vofT,         // (20000, 512)
           float* __restrict__ out)                // 1024 final + 20000*1024 hist
{
    const int tid = (int)threadIdx.x;
    const int cta = (int)blockIdx.x;          // cluster rank (grid = 1 cluster)
    const int r   = tid >> 2;                 // local row 0..63
    const int q   = tid & 3;                  // column quarter 0..3
    const int j   = cta * ROWSPC + r;         // global region of this row

    uint32_t sb;
    asm("{ .reg .u64 t; cvta.to.shared.u64 t, %1; cvt.u32.u64 %0, t; }"
        : "=r"(sb) : "l"(smx));
    const uint32_t mb0 = sb + MBAR_OFF;
    const uint32_t mb1 = sb + MBAR_OFF + 8;

    if (tid == 0) {
        asm volatile("mbarrier.init.shared.b64 [%0], %1;" :: "r"(mb0), "r"(512));
        asm volatile("mbarrier.init.shared.b64 [%0], %1;" :: "r"(mb1), "r"(512));
    }

    // ---- Con row segment -> 64 packed f32x2 registers (128 fp32) ----
    unsigned long long c64[64];
    {
        const ulonglong2* src =
            (const ulonglong2*)(Con + (size_t)j * NREG + (size_t)q * 128);
        #pragma unroll
        for (int it = 0; it < 32; ++it) {
            ulonglong2 t2 = src[it];
            c64[2*it] = t2.x; c64[2*it+1] = t2.y;
        }
    }

    // ---- init x (parity 0) : padded layout x[k] @ (k>>7)*QF + (k&127) ----
    for (int k = tid; k < NREG; k += NTHR)
        smx[(k >> 7) * QF + (k & 127)] = init_state[2 * k];

    // ---- per-region state replicated on all 4 lanes of the row ----
    float sE = init_state[2 * j];
    float sI = init_state[2 * j + 1];

    // local byte address of region j's x slot, both parities
    const uint32_t slotOff = (uint32_t)(((j >> 7) * QF + (j & 127)) * 4);
    const uint32_t slot0 = sb + slotOff;
    const uint32_t slot1 = sb + (uint32_t)(PF * 4) + slotOff;

    // this lane broadcasts to cluster ranks d0, d1
    const int d0 = 2 * q;
    const int d1 = 2 * q + 1;

    // one full cluster rendezvous: mbarrier inits + x parity-0 visible
    asm volatile("barrier.cluster.arrive.aligned;" ::: "memory");
    asm volatile("barrier.cluster.wait.aligned;"   ::: "memory");

    float v = __ldg(vofT + j);   // noise for step 0 (same addr all 4 lanes)
    float2* outv = (float2*)out;

    for (int t = 0; t < NSTEPS; ++t) {
        const int p = t & 1;

        // ---- matvec: 128 cols/thread, C in regs, x from smem (f32x2) ----
        const ulonglong2* x2 = (const ulonglong2*)
            ((const char*)smx + (p ? PF * 4 : 0) + q * (QF * 4));
        unsigned long long a0 = 0ULL, a1 = 0ULL, a2 = 0ULL, a3 = 0ULL;
        #pragma unroll
        for (int it = 0; it < 16; ++it) {
            ulonglong2 xa = x2[2*it];
            ulonglong2 xb = x2[2*it+1];
            a0 = ffma2(c64[4*it+0], xa.x, a0);
            a1 = ffma2(c64[4*it+1], xa.y, a1);
            a2 = ffma2(c64[4*it+2], xb.x, a2);
            a3 = ffma2(c64[4*it+3], xb.y, a3);
        }
        float acc = (fsum2(a0) + fsum2(a1)) + (fsum2(a2) + fsum2(a3));
        acc += __shfl_xor_sync(0xffffffffu, acc, 1);
        acc += __shfl_xor_sync(0xffffffffu, acc, 2);
        // all 4 lanes now hold the identical full row dot product

        // ---- epilogue (replicated on all 4 lanes, bit-identical) ----
        float I_E = 0.382f  + 0.21f * sE + 3.0f * acc - sI;   // LAMBDA=0 folded
        float I_I = 0.2674f + 0.15f * sE - sI;
        float rE = Hfun(I_E, 310.0f, 125.0f, 0.16f,  1e9f);
        float rI = Hfun(I_I, 615.0f, 177.0f, 0.087f, 1e5f);
        float dE = -sE * 0.01f + (1.0f - sE) * 6.41e-4f * rE + 0.01f * v;
        float dI = -sI * 0.1f  + 1.0e-3f * rI + 0.01f * v;
        sE = fmaf(1e-4f, dE, sE);
        sI = fmaf(1e-4f, dI, sI);

        // ---- broadcast new S_E into buffer p^1 of 2 CTAs + arrive ----
        {
            const uint32_t dslot = p ? slot0 : slot1;          // buffer p^1
            const uint32_t mbl   = p ? mb1   : mb0;            // mbar[t&1]
            uint32_t ra;
            asm("mapa.shared::cluster.u32 %0, %1, %2;" : "=r"(ra) : "r"(dslot), "r"(d0));
            asm volatile("st.shared::cluster.f32 [%0], %1;" :: "r"(ra), "f"(sE));
            asm("mapa.shared::cluster.u32 %0, %1, %2;" : "=r"(ra) : "r"(dslot), "r"(d1));
            asm volatile("st.shared::cluster.f32 [%0], %1;" :: "r"(ra), "f"(sE));
            asm("mapa.shared::cluster.u32 %0, %1, %2;" : "=r"(ra) : "r"(mbl), "r"(d0));
            asm volatile("mbarrier.arrive.release.cluster.shared::cluster.b64 _, [%0];"
                         :: "r"(ra) : "memory");
            asm("mapa.shared::cluster.u32 %0, %1, %2;" : "=r"(ra) : "r"(mbl), "r"(d1));
            asm volatile("mbarrier.arrive.release.cluster.shared::cluster.b64 _, [%0];"
                         :: "r"(ra) : "memory");
        }

        // history (lead lane only; fire-and-forget STG)
        if (q == 0)
            outv[512 + (size_t)t * NREG + j] = make_float2(sE, sI);

        // prefetch next noise sample before blocking on the barrier
        const int tn = (t + 1 < NSTEPS) ? (t + 1) : t;
        float vn = __ldg(vofT + (size_t)tn * NREG + j);

        // ---- wait for all 512 region broadcasts of this step ----
        {
            const uint32_t mbw = p ? mb1 : mb0;
            const uint32_t par = (uint32_t)((t >> 1) & 1);
            asm volatile(
                "{\n\t"
                ".reg .pred P;\n"
                "WL_%=:\n\t"
                "mbarrier.try_wait.parity.acquire.cluster.shared::cta.b64 P, [%0], %1, 0x989680;\n\t"
                "@!P bra WL_%=;\n\t"
                "}"
                :: "r"(mbw), "r"(par) : "memory");
        }

        v = vn;
    }

    // final state_vals (first 512 float2 of d_out)
    if (q == 0) outv[j] = make_float2(sE, sI);
}

extern "C" void kernel_launch(void* const* d_in, const int* in_sizes, int n_in,
                              void* d_out, int out_size) {
    const float* init = nullptr;
    const float* con  = nullptr;
    const float* v    = nullptr;
    for (int i = 0; i < n_in; ++i) {
        if      (in_sizes[i] == NREG * 2)      init = (const float*)d_in[i];
        else if (in_sizes[i] == NREG * NREG)   con  = (const float*)d_in[i];
        else if (in_sizes[i] == NSTEPS * NREG) v    = (const float*)d_in[i];
    }
    rww_kernel<<<NCTAS, NTHR, SMEM_BYTES>>>(init, con, v, (float*)d_out);
    (void)out_size;
}

// round 3
// speedup vs baseline: 1.4383x; 1.4383x over previous
#include <cuda_runtime.h>
#include <cstdint>
#include <cstddef>

// RWW whole-brain sim, 8-CTA cluster, Con_Mtx register-resident (128 f32/thread).
// R3: barrier.cluster sync (HW-aggregated, R1-proven) + ffma2 matvec +
//     fast-math epilogue + PACKED float4 DSMEM broadcast (112x16B received
//     per CTA/step instead of 448x4B) with hoisted mapa, and history/noise
//     issued between cluster arrive and wait.

#define NREG    512
#define NSTEPS  20000
#define NCTAS   8
#define ROWSPC  64
#define NTHR    256

// x-vector smem layout (floats): quarter stride QF floats. QF*4 = 2576 B
// == 16 mod 128 -> the 4 column-quarter lanes of a warp hit distinct 16B
// bank groups with 8-way broadcast => conflict-free LDS.128.
#define QF 644
#define PF 2576
#define SMEM_BYTES (2 * PF * 4)   // 20608 B (two parity buffers)

__device__ __forceinline__ unsigned long long ffma2(
    unsigned long long a, unsigned long long b, unsigned long long c) {
    unsigned long long d;
    asm("fma.rn.f32x2 %0, %1, %2, %3;" : "=l"(d) : "l"(a), "l"(b), "l"(c));
    return d;
}

__device__ __forceinline__ float fsum2(unsigned long long a) {
    float2 f = *reinterpret_cast<float2*>(&a);
    return f.x + f.y;
}

__device__ __forceinline__ float Hfun(float I, float a, float b, float d, float bigc) {
    float x     = fmaf(a, I, -b);
    float numer = fabsf(x) + 1e-9f;
    float neg   = -d * x;
    float e     = __expf(fminf(neg, 51.0f));
    float den_s = fabsf(1.0f - e) + 1e-9f * d;
    float den_b = fabsf(1.0f - bigc * neg) + 1e-9f * d;
    float denom = (neg > 50.0f) ? den_b : den_s;
    return __fdividef(numer, denom);
}

extern __shared__ float smx[];

__global__ void __launch_bounds__(NTHR, 1) __cluster_dims__(NCTAS, 1, 1)
rww_kernel(const float* __restrict__ init_state,   // (512, 2)
           const float* __restrict__ Con,          // (512, 512) row-major
           const float* __restrict__ vofT,         // (20000, 512)
           float* __restrict__ out)                // 1024 final + 20000*1024 hist
{
    const int tid = (int)threadIdx.x;
    const int cta = (int)blockIdx.x;          // cluster rank (grid = 1 cluster)
    const int r   = tid >> 2;                 // local row 0..63
    const int q   = tid & 3;                  // column quarter 0..3
    const int j   = cta * ROWSPC + r;         // global region of this row

    uint32_t sb;
    asm("{ .reg .u64 t; cvta.to.shared.u64 t, %1; cvt.u32.u64 %0, t; }"
        : "=r"(sb) : "l"(smx));

    // ---- Con row segment -> 64 packed f32x2 registers (128 fp32) ----
    unsigned long long c64[64];
    {
        const ulonglong2* src =
            (const ulonglong2*)(Con + (size_t)j * NREG + (size_t)q * 128);
        #pragma unroll
        for (int it = 0; it < 32; ++it) {
            ulonglong2 t2 = src[it];
            c64[2*it] = t2.x; c64[2*it+1] = t2.y;
        }
    }

    // ---- init x (parity 0), full vector locally in every CTA ----
    for (int k = tid; k < NREG; k += NTHR)
        smx[(k >> 7) * QF + (k & 127)] = init_state[2 * k];

    // ---- per-region state replicated on all 4 lanes of the row ----
    float sE = init_state[2 * j];
    float sI = init_state[2 * j + 1];

    // local float index of region j's x slot (within one parity buffer)
    const int slotF = (j >> 7) * QF + (j & 127);

    // ---- packed remote-copy assignment: threads 0..127 ----
    // this CTA's 64-region block lives at float index sbase.. sbase+63
    const int sbase = (cta >> 1) * QF + (cta & 1) * 64;   // 16B-aligned
    const int dst   = tid >> 4;          // destination cluster rank 0..7
    const int chunk = tid & 15;          // float4 chunk 0..15
    const bool docopy = (tid < 128) && (dst != cta);
    // local source addresses (both parities), as float4*
    const float4* src0 = (const float4*)(smx + sbase) + chunk;
    const float4* src1 = (const float4*)(smx + PF + sbase) + chunk;
    // remote destination SMEM addresses (both parities), hoisted mapa
    uint32_t rem0 = 0, rem1 = 0;
    if (docopy) {
        uint32_t a0 = sb + (uint32_t)((sbase + chunk * 4) * 4);
        uint32_t a1 = a0 + (uint32_t)(PF * 4);
        asm("mapa.shared::cluster.u32 %0, %1, %2;" : "=r"(rem0) : "r"(a0), "r"(dst));
        asm("mapa.shared::cluster.u32 %0, %1, %2;" : "=r"(rem1) : "r"(a1), "r"(dst));
    }

    __syncthreads();   // local parity-0 x ready

    float v = __ldg(vofT + j);   // noise for step 0
    float2* outv = (float2*)out;

    for (int t = 0; t < NSTEPS; ++t) {
        const int p = t & 1;

        // ---- matvec: 128 cols/thread, Con in regs, x from smem (f32x2) ----
        const ulonglong2* x2 = (const ulonglong2*)
            ((const char*)smx + (p ? PF * 4 : 0) + q * (QF * 4));
        unsigned long long a0 = 0ULL, a1 = 0ULL, a2 = 0ULL, a3 = 0ULL;
        #pragma unroll
        for (int it = 0; it < 16; ++it) {
            ulonglong2 xa = x2[2*it];
            ulonglong2 xb = x2[2*it+1];
            a0 = ffma2(c64[4*it+0], xa.x, a0);
            a1 = ffma2(c64[4*it+1], xa.y, a1);
            a2 = ffma2(c64[4*it+2], xb.x, a2);
            a3 = ffma2(c64[4*it+3], xb.y, a3);
        }
        float acc = (fsum2(a0) + fsum2(a1)) + (fsum2(a2) + fsum2(a3));
        acc += __shfl_xor_sync(0xffffffffu, acc, 1);
        acc += __shfl_xor_sync(0xffffffffu, acc, 2);
        // all 4 lanes of the row now hold the full dot product

        // ---- epilogue (replicated on all 4 lanes, bit-identical) ----
        float I_E = 0.382f  + 0.21f * sE + 3.0f * acc - sI;   // LAMBDA=0 folded
        float I_I = 0.2674f + 0.15f * sE - sI;
        float rE = Hfun(I_E, 310.0f, 125.0f, 0.16f,  1e9f);
        float rI = Hfun(I_I, 615.0f, 177.0f, 0.087f, 1e5f);
        float dE = -sE * 0.01f + (1.0f - sE) * 6.41e-4f * rE + 0.01f * v;
        float dI = -sI * 0.1f  + 1.0e-3f * rI + 0.01f * v;
        sE = fmaf(1e-4f, dE, sE);
        sI = fmaf(1e-4f, dI, sI);

        // ---- stage new S_E locally into parity p^1 buffer ----
        if (q == 0)
            smx[(p ? 0 : PF) + slotF] = sE;
        __syncthreads();

        // ---- packed broadcast: 16B st.shared::cluster per copy thread ----
        if (docopy) {
            float4 val = p ? *src0 : *src1;          // staged block, parity p^1
            uint32_t ra = p ? rem0 : rem1;
            asm volatile("st.shared::cluster.v4.f32 [%0], {%1, %2, %3, %4};"
                         :: "r"(ra), "f"(val.x), "f"(val.y), "f"(val.z), "f"(val.w)
                         : "memory");
        }

        // arrive (release: orders our DSMEM stores cluster-wide)
        asm volatile("barrier.cluster.arrive.aligned;" ::: "memory");

        // overlap with the barrier: history STG + next noise prefetch
        if (q == 0)
            outv[512 + (size_t)t * NREG + j] = make_float2(sE, sI);
        const int tn = (t + 1 < NSTEPS) ? (t + 1) : t;
        float vn = __ldg(vofT + (size_t)tn * NREG + j);

        // wait (acquire: peers' stores for parity p^1 now visible)
        asm volatile("barrier.cluster.wait.aligned;" ::: "memory");

        v = vn;
    }

    // final state_vals (first 512 float2 of d_out)
    if (q == 0) outv[j] = make_float2(sE, sI);
}

extern "C" void kernel_launch(void* const* d_in, const int* in_sizes, int n_in,
                              void* d_out, int out_size) {
    const float* init = nullptr;
    const float* con  = nullptr;
    const float* v    = nullptr;
    for (int i = 0; i < n_in; ++i) {
        if      (in_sizes[i] == NREG * 2)      init = (const float*)d_in[i];
        else if (in_sizes[i] == NREG * NREG)   con  = (const float*)d_in[i];
        else if (in_sizes[i] == NSTEPS * NREG) v    = (const float*)d_in[i];
    }
    rww_kernel<<<NCTAS, NTHR, SMEM_BYTES>>>(init, con, v, (float*)d_out);
    (void)out_size;
}